// round 13
// baseline (speedup 1.0000x reference)
#include <cuda_runtime.h>
#include <math.h>

// Problem constants (fixed by the dataset)
#define DIM      2048
#define SEQ      8192
#define NBLK     16               // blocks; each owns DIM/NBLK = 128 dims
#define TPB      256              // 8 token-groups x 32 dim-lanes
#define NLANE    32               // lanes per group; 32 * float4 = 128 dims
#define NGRP     8                // token groups per block
#define NTOK_FIX 48               // newest tokens processed unconditionally
// NTOK_FIX truncation: d^48 ~ 7e-8 for the actual decay -> ~1e-7 relative
// contribution, ~1e4x under the 1e-3 tolerance. Tokens beyond NTOK_FIX are
// handled by the guarded tail loop whenever their weight exceeds 2^-TCUT
// (general-decay correctness; empty for the actual input).
#define TCUT     20.0f

__device__ __forceinline__ float sigmoidf_(float x) {
    return 1.0f / (1.0f + expf(-x));
}

// out[dim] = tanh( (1-d) * sum_t d^t * emb[idx[SEQ-1-t]][dim] )
//
// FINAL KERNEL (best measured across 13 rounds; bench 6.62-6.91us band,
// harness-floor-bound):
//  - Algorithm: the reference's 8192-step sequential EMA equals a geometric-
//    weighted sum over tokens; weights below ~1e-7 are invisible at the
//    1e-3 tolerance, so only the newest 48 tokens are gathered.
//  - One fused launch (single graph node). 16 blocks x 256 threads,
//    8 token-groups of 32 dim-lanes: enough warp-level parallelism that the
//    ~12 loads/thread pipeline fully (collapsing token-parallelism measured
//    2.5x slower; doubling it measured neutral-to-worse).
//  - Decay scalar load issued first; its sigmoid/log2 chain overlaps the
//    gather stream, whose addresses depend only on thread ids.
//  - Fixed-order smem reduction + tanh epilogue in group 0.
__global__ void __launch_bounds__(TPB)
impulse_fused_kernel(const int* __restrict__ idx,
                     const float* __restrict__ emb,
                     const float* __restrict__ ssm_decay,
                     float* __restrict__ out)
{
    __shared__ float4 red[NGRP - 1][NLANE];

    // Issue the decay load FIRST so it flies alongside the gather stream.
    const float dec_raw = __ldg(ssm_decay);

    const int lane = threadIdx.x & (NLANE - 1);   // dim lane within block
    const int tg   = threadIdx.x >> 5;            // token group 0..7

    const int dim = blockIdx.x * (NLANE * 4) + lane * 4;

    // ---- Load stream: addresses depend ONLY on thread ids. All 6 idx
    // loads + 6 emb loads issue immediately, overlapping the decay math. ----
    const int NPT = NTOK_FIX / NGRP;              // 6 tokens per thread
    float4 x[NPT];
    #pragma unroll
    for (int j = 0; j < NPT; ++j) {
        const int t = tg + j * NGRP;
        const long long row =
            (long long)__ldg(idx + (SEQ - 1 - t)) * (long long)DIM;
        x[j] = *reinterpret_cast<const float4*>(emb + row + dim);
    }

    // ---- Decay chain: concurrent with the loads above. ----
    const float d   = sigmoidf_(dec_raw);
    const float l2d = log2f(d);                   // <= 0 since 0 < d <= 1

    const float wstep = exp2f((float)NGRP * l2d); // d^8
    float w = exp2f((float)tg * l2d);             // d^tg

    float ax = 0.0f, ay = 0.0f, az = 0.0f, aw = 0.0f;
    #pragma unroll
    for (int j = 0; j < NPT; ++j) {
        ax = fmaf(w, x[j].x, ax);
        ay = fmaf(w, x[j].y, ay);
        az = fmaf(w, x[j].z, az);
        aw = fmaf(w, x[j].w, aw);
        w *= wstep;
    }

    // ---- General-decay tail (empty for the actual input). ----
    const float nt = TCUT / (-l2d);               // inf if d == 1
    const int ntok = (nt >= (float)SEQ) ? SEQ : ((int)nt + 1);
    for (int t = NTOK_FIX + tg; t < ntok; t += NGRP) {
        const long long row =
            (long long)__ldg(idx + (SEQ - 1 - t)) * (long long)DIM;
        const float4 v = *reinterpret_cast<const float4*>(emb + row + dim);
        const float wt = exp2f((float)t * l2d);
        ax = fmaf(wt, v.x, ax);
        ay = fmaf(wt, v.y, ay);
        az = fmaf(wt, v.z, az);
        aw = fmaf(wt, v.w, aw);
    }

    // ---- Cross-group reduction (fixed order -> deterministic). ----
    if (tg > 0) {
        float4 v; v.x = ax; v.y = ay; v.z = az; v.w = aw;
        red[tg - 1][lane] = v;
    }
    __syncthreads();

    if (tg == 0) {
        #pragma unroll
        for (int g = 0; g < NGRP - 1; ++g) {
            const float4 v = red[g][lane];
            ax += v.x; ay += v.y; az += v.z; aw += v.w;
        }
        const float s = 1.0f - d;
        float4 o;
        o.x = tanhf(s * ax);
        o.y = tanhf(s * ay);
        o.z = tanhf(s * az);
        o.w = tanhf(s * aw);
        *reinterpret_cast<float4*>(out + dim) = o;
    }
}

extern "C" void kernel_launch(void* const* d_in, const int* in_sizes, int n_in,
                              void* d_out, int out_size)
{
    const int*   indices   = (const int*)d_in[0];
    const float* embedding = (const float*)d_in[1];
    const float* ssm_decay = (const float*)d_in[2];
    float*       out       = (float*)d_out;

    (void)in_sizes; (void)n_in; (void)out_size;

    impulse_fused_kernel<<<NBLK, TPB>>>(indices, embedding, ssm_decay, out);
}

// round 14
// speedup vs baseline: 1.0435x; 1.0435x over previous
#include <cuda_runtime.h>
#include <math.h>

// Problem constants (fixed by the dataset)
#define DIM      2048
#define SEQ      8192
#define NBLK     16               // blocks; each owns DIM/NBLK = 128 dims
#define TPB      256              // 8 warps; each warp owns 16 dims
#define NGRP     8                // token groups (lane>>2 within each warp)
#define NTOK_FIX 48               // newest tokens processed unconditionally
// NTOK_FIX truncation: d^48 ~ 7e-8 for the actual decay -> ~1e-7 relative
// contribution, ~1e4x under the 1e-3 tolerance. Tokens beyond NTOK_FIX are
// handled by the guarded tail loop whenever their weight exceeds 2^-TCUT
// (general-decay correctness; empty for the actual input).
#define TCUT     20.0f

__device__ __forceinline__ float sigmoidf_(float x) {
    return 1.0f / (1.0f + expf(-x));
}

// out[dim] = tanh( (1-d) * sum_t d^t * emb[idx[SEQ-1-t]][dim] )
//
// Warp-autonomous variant: within each warp, lanes split as 8 token-groups
// (lane>>2) x 4 dim-quads (lane&3). The cross-group reduction is a 3-level
// __shfl_xor butterfly INSIDE the warp — no __syncthreads, no shared memory,
// so each warp stores its 16 dims the moment its own loads drain instead of
// waiting on the block's slowest warp at a barrier. Token-parallelism (8x)
// is identical to the best measured config.
__global__ void __launch_bounds__(TPB)
impulse_fused_kernel(const int* __restrict__ idx,
                     const float* __restrict__ emb,
                     const float* __restrict__ ssm_decay,
                     float* __restrict__ out)
{
    // Issue the decay load FIRST so it flies alongside the gather stream.
    const float dec_raw = __ldg(ssm_decay);

    const int lane = threadIdx.x & 31;
    const int wid  = threadIdx.x >> 5;            // warp 0..7
    const int tg   = lane >> 2;                   // token group 0..7
    const int quad = lane & 3;                    // dim quad 0..3

    // Each warp owns 16 dims: block*128 + warp*16 + quad*4.
    const int dim = blockIdx.x * 128 + wid * 16 + quad * 4;

    // ---- Load stream: addresses depend ONLY on thread ids. All 6 idx
    // loads + 6 emb loads issue immediately, overlapping the decay math. ----
    const int NPT = NTOK_FIX / NGRP;              // 6 tokens per thread
    float4 x[NPT];
    #pragma unroll
    for (int j = 0; j < NPT; ++j) {
        const int t = tg + j * NGRP;
        const long long row =
            (long long)__ldg(idx + (SEQ - 1 - t)) * (long long)DIM;
        x[j] = *reinterpret_cast<const float4*>(emb + row + dim);
    }

    // ---- Decay chain: concurrent with the loads above. ----
    const float d   = sigmoidf_(dec_raw);
    const float l2d = log2f(d);                   // <= 0 since 0 < d <= 1

    const float wstep = exp2f((float)NGRP * l2d); // d^8
    float w = exp2f((float)tg * l2d);             // d^tg

    float ax = 0.0f, ay = 0.0f, az = 0.0f, aw = 0.0f;
    #pragma unroll
    for (int j = 0; j < NPT; ++j) {
        ax = fmaf(w, x[j].x, ax);
        ay = fmaf(w, x[j].y, ay);
        az = fmaf(w, x[j].z, az);
        aw = fmaf(w, x[j].w, aw);
        w *= wstep;
    }

    // ---- General-decay tail (empty for the actual input). ----
    const float nt = TCUT / (-l2d);               // inf if d == 1
    const int ntok = (nt >= (float)SEQ) ? SEQ : ((int)nt + 1);
    for (int t = NTOK_FIX + tg; t < ntok; t += NGRP) {
        const long long row =
            (long long)__ldg(idx + (SEQ - 1 - t)) * (long long)DIM;
        const float4 v = *reinterpret_cast<const float4*>(emb + row + dim);
        const float wt = exp2f((float)t * l2d);
        ax = fmaf(wt, v.x, ax);
        ay = fmaf(wt, v.y, ay);
        az = fmaf(wt, v.z, az);
        aw = fmaf(wt, v.w, aw);
    }

    // ---- In-warp butterfly across token groups (lanes differing in
    // bits 2..4 share a dim-quad). Deterministic fixed-order tree. ----
    #pragma unroll
    for (int off = 4; off <= 16; off <<= 1) {
        ax += __shfl_xor_sync(0xFFFFFFFFu, ax, off);
        ay += __shfl_xor_sync(0xFFFFFFFFu, ay, off);
        az += __shfl_xor_sync(0xFFFFFFFFu, az, off);
        aw += __shfl_xor_sync(0xFFFFFFFFu, aw, off);
    }

    if (tg == 0) {                                // lanes 0..3 write
        const float s = 1.0f - d;
        float4 o;
        o.x = tanhf(s * ax);
        o.y = tanhf(s * ay);
        o.z = tanhf(s * az);
        o.w = tanhf(s * aw);
        *reinterpret_cast<float4*>(out + dim) = o;
    }
}

extern "C" void kernel_launch(void* const* d_in, const int* in_sizes, int n_in,
                              void* d_out, int out_size)
{
    const int*   indices   = (const int*)d_in[0];
    const float* embedding = (const float*)d_in[1];
    const float* ssm_decay = (const float*)d_in[2];
    float*       out       = (float*)d_out;

    (void)in_sizes; (void)n_in; (void)out_size;

    impulse_fused_kernel<<<NBLK, TPB>>>(indices, embedding, ssm_decay, out);
}